// round 7
// baseline (speedup 1.0000x reference)
#include <cuda_runtime.h>
#include <math.h>

// ---------------------------------------------------------------------------
// InteractionPredictor: e3nn-style equivariant GNN, fully fused fp32.
// R6: 64 edges / 128-thread block; 4 warps each own a k-chunk of 16 hidden
// units (registers). 2 edges per lane. Cross-warp reduction via NON-ATOMIC
// per-warp smem slices + cooperative tree-add (phased scalar/vector to stay
// under 48KB static smem). Smem atomics eliminated (they were the L1
// bottleneck: spread-addr ATOMS ~2cyc/lane).
// ---------------------------------------------------------------------------

#define TBE    128         /* threads per edge block      */
#define EPB    64          /* edges per block             */
#define KC     16          /* k-chunk per warp (4 warps)  */
#define NW     4           /* warps per block             */
#define NF     40
#define NMAX   16384
#define EIMAX  65536

__device__ float g_node[NMAX * NF];
__device__ float g_msgs[NMAX * NF];
__device__ float g_lig [EIMAX * NF];

#define C24    0.20412414523193154f   /* sqrt(1/24)  */
#define C24S3  0.35355339059327373f   /* sqrt(1/8)   */
#define INVS3  0.57735026918962576f   /* 1/sqrt(3)   */
#define PWREC  0.05590169943749474f   /* 1/sqrt(320) */
#define DEMBC  8.4335731f             /* 1.14136*e^2 */
#define INV32  0.17677669529663687f   /* 1/sqrt(32)  */

__device__ __forceinline__ float siluN(float x) {
    return x * (1.0f / (1.0f + __expf(-x))) * 1.6789717f;
}

// ---------------------------------------------------------------------------
// node embedding; also zeroes the message accumulator for step 0
// ---------------------------------------------------------------------------
__global__ void k_embed(const float* __restrict__ x, int N, int A,
                        const float* __restrict__ W0, const float* __restrict__ W1) {
    int n = blockIdx.x * blockDim.x + threadIdx.x;
    if (n >= N) return;
    float inv = rsqrtf((float)A);
    float a[16];
#pragma unroll
    for (int b = 0; b < 16; b++) a[b] = (b < A) ? x[n * A + b] : 0.0f;
    float h[64];
#pragma unroll 4
    for (int k = 0; k < 64; k++) {
        float s = 0.0f;
#pragma unroll
        for (int b = 0; b < 16; b++)
            if (b < A) s += a[b] * W0[b * 64 + k];
        h[k] = siluN(s * inv) * 0.125f;
    }
    float* nr = g_node + n * NF;
#pragma unroll
    for (int w = 0; w < 16; w++) {
        float s = 0.0f;
#pragma unroll 8
        for (int k = 0; k < 64; k++) s += h[k] * W1[k * 16 + w];
        nr[w] = s;
    }
#pragma unroll
    for (int t = 0; t < 24; t++) nr[16 + t] = 0.0f;
    float* mr = g_msgs + n * NF;
#pragma unroll
    for (int t = 0; t < NF; t++) mr[t] = 0.0f;
}

// ---------------------------------------------------------------------------
// node update; re-zeroes this node's message row after consuming it
// ---------------------------------------------------------------------------
__global__ void k_update(int N, const float* __restrict__ imp, float degf,
                         const float* __restrict__ W0, const float* __restrict__ W1,
                         float gmul) {
    int n = blockIdx.x * blockDim.x + threadIdx.x;
    if (n >= N) return;
    float scale = imp[0] * rsqrtf(degf);
    float* nr = g_node + n * NF;
    float* mr = g_msgs + n * NF;
    float a[32];
#pragma unroll
    for (int t = 0; t < 16; t++) a[t] = mr[t] * scale;
#pragma unroll
    for (int t = 0; t < 16; t++) a[16 + t] = nr[t];
    float ge[24];
#pragma unroll
    for (int t = 0; t < 24; t++) ge[t] = (mr[16 + t] * scale + nr[16 + t]) * gmul;
#pragma unroll
    for (int t = 0; t < NF; t++) mr[t] = 0.0f;
    float h[64];
#pragma unroll 2
    for (int k = 0; k < 64; k++) {
        float s = 0.0f;
#pragma unroll
        for (int b = 0; b < 32; b++) s += a[b] * W0[b * 64 + k];
        h[k] = siluN(s * INV32) * 0.125f;
    }
    float sc[16];
#pragma unroll
    for (int w = 0; w < 16; w++) {
        float s = 0.0f;
#pragma unroll 8
        for (int k = 0; k < 64; k++) s += h[k] * W1[k * 16 + w];
        sc[w] = s;
    }
#pragma unroll
    for (int w = 0; w < 16; w++) nr[w] = sc[w];
#pragma unroll
    for (int t = 0; t < 24; t++) nr[16 + t] = ge[t];
}

// ---------------------------------------------------------------------------
__device__ __forceinline__ void demb_compute(float d, float* a) {
    float tt = d * 4.2f;
#pragma unroll
    for (int i = 0; i < 20; i++) {
        float diff = tt - (float)(i + 1);
        float p = diff + 1.0f, q = 1.0f - diff;
        float s1 = (p > 0.0f) ? __expf(-1.0f / p) : 0.0f;
        float s2 = (q > 0.0f) ? __expf(-1.0f / q) : 0.0f;
        a[i] = DEMBC * s1 * s2;
    }
}

// ---------------------------------------------------------------------------
// Scalar-output fold phase (blocks A+B -> os[16]); writes this warp's slice.
// slice: base of this warp's 16*EPB region.
// ---------------------------------------------------------------------------
__device__ __forceinline__ void fold_scalar(
    const float* __restrict__ ha, const float* __restrict__ hb, int lane,
    const float* __restrict__ shN, const float* __restrict__ shR,
    const float* __restrict__ W1k, float* __restrict__ slice)
{
    float ra0 = shR[lane],      ra1 = shR[EPB + lane],      ra2 = shR[2 * EPB + lane];
    float rb0 = shR[lane + 32], rb1 = shR[EPB + lane + 32], rb2 = shR[2 * EPB + lane + 32];

    float osA[16], osB[16];
#pragma unroll
    for (int t = 0; t < 16; t++) { osA[t] = 0.0f; osB[t] = 0.0f; }

    // Block A: 0e x 0e -> 0e ; cols [u*16, +16), u<16
#pragma unroll 1
    for (int u = 0; u < 16; u++) {
        float wa[16], wb[16];
#pragma unroll
        for (int t = 0; t < 16; t++) { wa[t] = 0.0f; wb[t] = 0.0f; }
        const float* base = W1k + u * 16;
#pragma unroll 4
        for (int j = 0; j < KC; j++) {
            const float4* p = reinterpret_cast<const float4*>(base + j * 576);
            float4 q0 = __ldg(p), q1 = __ldg(p + 1), q2 = __ldg(p + 2), q3 = __ldg(p + 3);
            float A = ha[j], Bv = hb[j];
            wa[0]+=A*q0.x; wa[1]+=A*q0.y; wa[2]+=A*q0.z; wa[3]+=A*q0.w;
            wa[4]+=A*q1.x; wa[5]+=A*q1.y; wa[6]+=A*q1.z; wa[7]+=A*q1.w;
            wa[8]+=A*q2.x; wa[9]+=A*q2.y; wa[10]+=A*q2.z; wa[11]+=A*q2.w;
            wa[12]+=A*q3.x; wa[13]+=A*q3.y; wa[14]+=A*q3.z; wa[15]+=A*q3.w;
            wb[0]+=Bv*q0.x; wb[1]+=Bv*q0.y; wb[2]+=Bv*q0.z; wb[3]+=Bv*q0.w;
            wb[4]+=Bv*q1.x; wb[5]+=Bv*q1.y; wb[6]+=Bv*q1.z; wb[7]+=Bv*q1.w;
            wb[8]+=Bv*q2.x; wb[9]+=Bv*q2.y; wb[10]+=Bv*q2.z; wb[11]+=Bv*q2.w;
            wb[12]+=Bv*q3.x; wb[13]+=Bv*q3.y; wb[14]+=Bv*q3.z; wb[15]+=Bv*q3.w;
        }
        float cfa = C24 * shN[u * EPB + lane];
        float cfb = C24 * shN[u * EPB + lane + 32];
#pragma unroll
        for (int t = 0; t < 16; t++) { osA[t] += cfa * wa[t]; osB[t] += cfb * wb[t]; }
    }

    // Block B: 1o x 1o -> 0e ; cols [256+u*16), u<8 ; coef C24*(xv_u . r)
#pragma unroll 1
    for (int u = 0; u < 8; u++) {
        float wa[16], wb[16];
#pragma unroll
        for (int t = 0; t < 16; t++) { wa[t] = 0.0f; wb[t] = 0.0f; }
        const float* base = W1k + 256 + u * 16;
#pragma unroll 4
        for (int j = 0; j < KC; j++) {
            const float4* p = reinterpret_cast<const float4*>(base + j * 576);
            float4 q0 = __ldg(p), q1 = __ldg(p + 1), q2 = __ldg(p + 2), q3 = __ldg(p + 3);
            float A = ha[j], Bv = hb[j];
            wa[0]+=A*q0.x; wa[1]+=A*q0.y; wa[2]+=A*q0.z; wa[3]+=A*q0.w;
            wa[4]+=A*q1.x; wa[5]+=A*q1.y; wa[6]+=A*q1.z; wa[7]+=A*q1.w;
            wa[8]+=A*q2.x; wa[9]+=A*q2.y; wa[10]+=A*q2.z; wa[11]+=A*q2.w;
            wa[12]+=A*q3.x; wa[13]+=A*q3.y; wa[14]+=A*q3.z; wa[15]+=A*q3.w;
            wb[0]+=Bv*q0.x; wb[1]+=Bv*q0.y; wb[2]+=Bv*q0.z; wb[3]+=Bv*q0.w;
            wb[4]+=Bv*q1.x; wb[5]+=Bv*q1.y; wb[6]+=Bv*q1.z; wb[7]+=Bv*q1.w;
            wb[8]+=Bv*q2.x; wb[9]+=Bv*q2.y; wb[10]+=Bv*q2.z; wb[11]+=Bv*q2.w;
            wb[12]+=Bv*q3.x; wb[13]+=Bv*q3.y; wb[14]+=Bv*q3.z; wb[15]+=Bv*q3.w;
        }
        float cfa = C24 * (shN[(16 + u * 3) * EPB + lane] * ra0 +
                           shN[(17 + u * 3) * EPB + lane] * ra1 +
                           shN[(18 + u * 3) * EPB + lane] * ra2);
        float cfb = C24 * (shN[(16 + u * 3) * EPB + lane + 32] * rb0 +
                           shN[(17 + u * 3) * EPB + lane + 32] * rb1 +
                           shN[(18 + u * 3) * EPB + lane + 32] * rb2);
#pragma unroll
        for (int t = 0; t < 16; t++) { osA[t] += cfa * wa[t]; osB[t] += cfb * wb[t]; }
    }

#pragma unroll
    for (int t = 0; t < 16; t++) {
        slice[t * EPB + lane]      = osA[t];
        slice[t * EPB + lane + 32] = osB[t];
    }
}

// ---------------------------------------------------------------------------
// Vector-output fold phase (blocks C+D -> ov[24]); writes this warp's slice.
// slice: base of this warp's 24*EPB region.
// ---------------------------------------------------------------------------
__device__ __forceinline__ void fold_vector(
    const float* __restrict__ ha, const float* __restrict__ hb, int lane,
    const float* __restrict__ shN, const float* __restrict__ shR,
    const float* __restrict__ W1k, float* __restrict__ slice)
{
    float ra0 = shR[lane],      ra1 = shR[EPB + lane],      ra2 = shR[2 * EPB + lane];
    float rb0 = shR[lane + 32], rb1 = shR[EPB + lane + 32], rb2 = shR[2 * EPB + lane + 32];

    float ovA[24], ovB[24];
#pragma unroll
    for (int t = 0; t < 24; t++) { ovA[t] = 0.0f; ovB[t] = 0.0f; }

    // Block C: 0e x 1o -> 1o ; cols [384+u*8), u<16
#pragma unroll 1
    for (int u = 0; u < 16; u++) {
        float wa[8], wb[8];
#pragma unroll
        for (int t = 0; t < 8; t++) { wa[t] = 0.0f; wb[t] = 0.0f; }
        const float* base = W1k + 384 + u * 8;
#pragma unroll 4
        for (int j = 0; j < KC; j++) {
            const float4* p = reinterpret_cast<const float4*>(base + j * 576);
            float4 q0 = __ldg(p), q1 = __ldg(p + 1);
            float A = ha[j], Bv = hb[j];
            wa[0]+=A*q0.x; wa[1]+=A*q0.y; wa[2]+=A*q0.z; wa[3]+=A*q0.w;
            wa[4]+=A*q1.x; wa[5]+=A*q1.y; wa[6]+=A*q1.z; wa[7]+=A*q1.w;
            wb[0]+=Bv*q0.x; wb[1]+=Bv*q0.y; wb[2]+=Bv*q0.z; wb[3]+=Bv*q0.w;
            wb[4]+=Bv*q1.x; wb[5]+=Bv*q1.y; wb[6]+=Bv*q1.z; wb[7]+=Bv*q1.w;
        }
        float cfa = C24S3 * shN[u * EPB + lane];
        float cfb = C24S3 * shN[u * EPB + lane + 32];
#pragma unroll
        for (int t = 0; t < 8; t++) {
            float sa = cfa * wa[t], sb = cfb * wb[t];
            ovA[t*3+0] += sa * ra0; ovA[t*3+1] += sa * ra1; ovA[t*3+2] += sa * ra2;
            ovB[t*3+0] += sb * rb0; ovB[t*3+1] += sb * rb1; ovB[t*3+2] += sb * rb2;
        }
    }

    // Block D: 1o x 0e -> 1o ; cols [512+u*8), u<8
#pragma unroll 1
    for (int u = 0; u < 8; u++) {
        float wa[8], wb[8];
#pragma unroll
        for (int t = 0; t < 8; t++) { wa[t] = 0.0f; wb[t] = 0.0f; }
        const float* base = W1k + 512 + u * 8;
#pragma unroll 4
        for (int j = 0; j < KC; j++) {
            const float4* p = reinterpret_cast<const float4*>(base + j * 576);
            float4 q0 = __ldg(p), q1 = __ldg(p + 1);
            float A = ha[j], Bv = hb[j];
            wa[0]+=A*q0.x; wa[1]+=A*q0.y; wa[2]+=A*q0.z; wa[3]+=A*q0.w;
            wa[4]+=A*q1.x; wa[5]+=A*q1.y; wa[6]+=A*q1.z; wa[7]+=A*q1.w;
            wb[0]+=Bv*q0.x; wb[1]+=Bv*q0.y; wb[2]+=Bv*q0.z; wb[3]+=Bv*q0.w;
            wb[4]+=Bv*q1.x; wb[5]+=Bv*q1.y; wb[6]+=Bv*q1.z; wb[7]+=Bv*q1.w;
        }
        float ca0 = C24 * shN[(16 + u * 3) * EPB + lane];
        float ca1 = C24 * shN[(17 + u * 3) * EPB + lane];
        float ca2 = C24 * shN[(18 + u * 3) * EPB + lane];
        float cb0 = C24 * shN[(16 + u * 3) * EPB + lane + 32];
        float cb1 = C24 * shN[(17 + u * 3) * EPB + lane + 32];
        float cb2 = C24 * shN[(18 + u * 3) * EPB + lane + 32];
#pragma unroll
        for (int t = 0; t < 8; t++) {
            ovA[t*3+0] += ca0 * wa[t]; ovA[t*3+1] += ca1 * wa[t]; ovA[t*3+2] += ca2 * wa[t];
            ovB[t*3+0] += cb0 * wb[t]; ovB[t*3+1] += cb1 * wb[t]; ovB[t*3+2] += cb2 * wb[t];
        }
    }

#pragma unroll
    for (int t = 0; t < 24; t++) {
        slice[t * EPB + lane]      = ovA[t];
        slice[t * EPB + lane + 32] = ovB[t];
    }
}

// ---------------------------------------------------------------------------
// message kernel: 64 edges / 128-thread block, 4 warps split k (16 each)
// ---------------------------------------------------------------------------
__global__ void __launch_bounds__(TBE, 3) k_msg(
    const float* __restrict__ pos,
    const int* __restrict__ srcI, const int* __restrict__ dstI,
    const float* __restrict__ eattr, int E, int B,
    const float* __restrict__ W0, const float* __restrict__ W1)
{
    __shared__ float shN[NF * EPB];          // 10 KB
    __shared__ float shS[NW * 24 * EPB];     // 24 KB (reused scalar->vector)
    __shared__ float shR[3 * EPB];
    __shared__ int   shSi[EPB];
    __shared__ int   shDi[EPB];

    int tid  = threadIdx.x;
    int lane = tid & 31;
    int warp = tid >> 5;
    int e0 = blockIdx.x * EPB;

    if (tid < EPB) {
        int e = min(e0 + tid, E - 1);
        int si = srcI[e], di = dstI[e];
        shSi[tid] = si; shDi[tid] = di;
        float vx = pos[di * 3 + 0] - pos[si * 3 + 0];
        float vy = pos[di * 3 + 1] - pos[si * 3 + 1];
        float vz = pos[di * 3 + 2] - pos[si * 3 + 2];
        float rn = rsqrtf(vx * vx + vy * vy + vz * vz);
        shR[tid]           = vx * rn;
        shR[EPB + tid]     = vy * rn;
        shR[2 * EPB + tid] = vz * rn;
    }
    __syncthreads();

    // preload source-node features [f][e]
    for (int i = tid; i < NF * EPB; i += TBE) {
        int e = i & (EPB - 1), f = i >> 6;
        shN[f * EPB + e] = g_node[shSi[e] * NF + f];
    }

    // this warp's k-chunk of h (registers, both edges)
    float ha[KC], hb[KC];
    {
        float inv = rsqrtf((float)B);
        int kb = warp * KC;
        int ea = min(e0 + lane, E - 1);
        int eb = min(e0 + lane + 32, E - 1);
        float aa[8], ab[8];
#pragma unroll
        for (int b = 0; b < 8; b++) {
            aa[b] = (b < B) ? eattr[ea * B + b] : 0.0f;
            ab[b] = (b < B) ? eattr[eb * B + b] : 0.0f;
        }
#pragma unroll
        for (int j = 0; j < KC; j++) {
            float sa = 0.0f, sb = 0.0f;
#pragma unroll
            for (int b = 0; b < 8; b++)
                if (b < B) {
                    float w = W0[b * 64 + kb + j];
                    sa += aa[b] * w; sb += ab[b] * w;
                }
            ha[j] = siluN(sa * inv) * 0.125f;
            hb[j] = siluN(sb * inv) * 0.125f;
        }
    }
    __syncthreads();

    const float* W1k = W1 + warp * KC * 576;

    // ---- scalar phase ----
    fold_scalar(ha, hb, lane, shN, shR, W1k, shS + warp * 16 * EPB);
    __syncthreads();
    for (int i = tid; i < 16 * EPB; i += TBE) {
        int e = i & (EPB - 1), f = i >> 6;
        float s = shS[i] + shS[16 * EPB + i] + shS[32 * EPB + i] + shS[48 * EPB + i];
        if (e0 + e < E) atomicAdd(&g_msgs[shDi[e] * NF + f], s);
    }
    __syncthreads();

    // ---- vector phase (slice buffer reused) ----
    fold_vector(ha, hb, lane, shN, shR, W1k, shS + warp * 24 * EPB);
    __syncthreads();
    for (int i = tid; i < 24 * EPB; i += TBE) {
        int e = i & (EPB - 1), f = i >> 6;
        float s = shS[i] + shS[24 * EPB + i] + shS[48 * EPB + i] + shS[72 * EPB + i];
        if (e0 + e < E) atomicAdd(&g_msgs[shDi[e] * NF + 16 + f], s);
    }
}

// ---------------------------------------------------------------------------
// ligand embedding
// ---------------------------------------------------------------------------
__global__ void __launch_bounds__(TBE, 3) k_lig(
    const float* __restrict__ pos,
    const int* __restrict__ recI, const int* __restrict__ ligI, int EI,
    const float* __restrict__ W0, const float* __restrict__ W1)
{
    __shared__ float shN[NF * EPB];
    __shared__ float shS[NW * 24 * EPB];
    __shared__ float shB[20 * EPB];
    __shared__ float shR[3 * EPB];
    __shared__ int   shLi[EPB];

    int tid  = threadIdx.x;
    int lane = tid & 31;
    int warp = tid >> 5;
    int e0 = blockIdx.x * EPB;

    if (tid < EPB) {
        int e = min(e0 + tid, EI - 1);
        int ri = recI[e], li = ligI[e];
        shLi[tid] = li;
        float vx = pos[li * 3 + 0] - pos[ri * 3 + 0];
        float vy = pos[li * 3 + 1] - pos[ri * 3 + 1];
        float vz = pos[li * 3 + 2] - pos[ri * 3 + 2];
        float d2 = vx * vx + vy * vy + vz * vz;
        float invd = rsqrtf(d2);
        shR[tid]           = vx * invd;
        shR[EPB + tid]     = vy * invd;
        shR[2 * EPB + tid] = vz * invd;
        float a[20];
        demb_compute(d2 * invd, a);
#pragma unroll
        for (int i = 0; i < 20; i++) shB[i * EPB + tid] = a[i];
    }
    __syncthreads();

    for (int i = tid; i < NF * EPB; i += TBE) {
        int e = i & (EPB - 1), f = i >> 6;
        shN[f * EPB + e] = g_node[shLi[e] * NF + f];
    }

    float ha[KC], hb[KC];
    {
        int kb = warp * KC;
        float aa[20], ab[20];
#pragma unroll
        for (int i = 0; i < 20; i++) {
            aa[i] = shB[i * EPB + lane];
            ab[i] = shB[i * EPB + lane + 32];
        }
#pragma unroll
        for (int j = 0; j < KC; j++) {
            float sa = 0.0f, sb = 0.0f;
#pragma unroll
            for (int i = 0; i < 20; i++) {
                float w = W0[i * 64 + kb + j];
                sa += aa[i] * w; sb += ab[i] * w;
            }
            ha[j] = siluN(sa) * 0.125f;
            hb[j] = siluN(sb) * 0.125f;
        }
    }
    __syncthreads();

    const float* W1k = W1 + warp * KC * 576;

    fold_scalar(ha, hb, lane, shN, shR, W1k, shS + warp * 16 * EPB);
    __syncthreads();
    for (int i = tid; i < 16 * EPB; i += TBE) {
        int e = i & (EPB - 1), f = i >> 6;
        float s = shS[i] + shS[16 * EPB + i] + shS[32 * EPB + i] + shS[48 * EPB + i];
        if (e0 + e < EI) g_lig[(e0 + e) * NF + f] = s;
    }
    __syncthreads();

    fold_vector(ha, hb, lane, shN, shR, W1k, shS + warp * 24 * EPB);
    __syncthreads();
    for (int i = tid; i < 24 * EPB; i += TBE) {
        int e = i & (EPB - 1), f = i >> 6;
        float s = shS[i] + shS[24 * EPB + i] + shS[48 * EPB + i] + shS[72 * EPB + i];
        if (e0 + e < EI) g_lig[(e0 + e) * NF + 16 + f] = s;
    }
}

// ---------------------------------------------------------------------------
// receptor TP readout: out[e][o], o<8 (single-phase slice reduction)
// ---------------------------------------------------------------------------
__global__ void __launch_bounds__(TBE, 3) k_rec(
    const float* __restrict__ pos,
    const int* __restrict__ recI, const int* __restrict__ ligI, int EI,
    const float* __restrict__ W0, const float* __restrict__ W1,
    float* __restrict__ out)
{
    __shared__ float shL [NF * EPB];
    __shared__ float shRn[NF * EPB];
    __shared__ float shB [20 * EPB];
    __shared__ float shS [NW * 8 * EPB];    // 8 KB
    __shared__ int   shRi[EPB];

    int tid  = threadIdx.x;
    int lane = tid & 31;
    int warp = tid >> 5;
    int e0 = blockIdx.x * EPB;

    if (tid < EPB) {
        int e = min(e0 + tid, EI - 1);
        int ri = recI[e], li = ligI[e];
        shRi[tid] = ri;
        float vx = pos[li * 3 + 0] - pos[ri * 3 + 0];
        float vy = pos[li * 3 + 1] - pos[ri * 3 + 1];
        float vz = pos[li * 3 + 2] - pos[ri * 3 + 2];
        float d2 = vx * vx + vy * vy + vz * vz;
        float a[20];
        demb_compute(d2 * rsqrtf(d2), a);
#pragma unroll
        for (int i = 0; i < 20; i++) shB[i * EPB + tid] = a[i];
    }
    __syncthreads();

    for (int i = tid; i < NF * EPB; i += TBE) {
        int e = i & (EPB - 1), f = i >> 6;
        int ec = min(e0 + e, EI - 1);
        shL [f * EPB + e] = g_lig[ec * NF + f];
        shRn[f * EPB + e] = g_node[shRi[e] * NF + f];
    }

    float ha[KC], hb[KC];
    {
        int kb = warp * KC;
        float aa[20], ab[20];
#pragma unroll
        for (int i = 0; i < 20; i++) {
            aa[i] = shB[i * EPB + lane];
            ab[i] = shB[i * EPB + lane + 32];
        }
#pragma unroll
        for (int j = 0; j < KC; j++) {
            float sa = 0.0f, sb = 0.0f;
#pragma unroll
            for (int i = 0; i < 20; i++) {
                float w = W0[i * 64 + kb + j];
                sa += aa[i] * w; sb += ab[i] * w;
            }
            ha[j] = siluN(sa) * 0.125f;
            hb[j] = siluN(sb) * 0.125f;
        }
    }
    __syncthreads();

    float accA[8], accB[8];
#pragma unroll
    for (int t = 0; t < 8; t++) { accA[t] = 0.0f; accB[t] = 0.0f; }
    const float* Wk = W1 + warp * KC * 2560;

    // scalar x scalar -> 8x0e : w1[u][v][o] at (u*16+v)*8
#pragma unroll 1
    for (int u = 0; u < 16; u++) {
        float lua = shL[u * EPB + lane];
        float lub = shL[u * EPB + lane + 32];
#pragma unroll 1
        for (int v = 0; v < 16; v++) {
            float wa[8], wb[8];
#pragma unroll
            for (int t = 0; t < 8; t++) { wa[t] = 0.0f; wb[t] = 0.0f; }
            const float* base = Wk + (u * 16 + v) * 8;
#pragma unroll 4
            for (int j = 0; j < KC; j++) {
                const float4* p = reinterpret_cast<const float4*>(base + j * 2560);
                float4 q0 = __ldg(p), q1 = __ldg(p + 1);
                float A = ha[j], Bv = hb[j];
                wa[0]+=A*q0.x; wa[1]+=A*q0.y; wa[2]+=A*q0.z; wa[3]+=A*q0.w;
                wa[4]+=A*q1.x; wa[5]+=A*q1.y; wa[6]+=A*q1.z; wa[7]+=A*q1.w;
                wb[0]+=Bv*q0.x; wb[1]+=Bv*q0.y; wb[2]+=Bv*q0.z; wb[3]+=Bv*q0.w;
                wb[4]+=Bv*q1.x; wb[5]+=Bv*q1.y; wb[6]+=Bv*q1.z; wb[7]+=Bv*q1.w;
            }
            float cfa = lua * shRn[v * EPB + lane];
            float cfb = lub * shRn[v * EPB + lane + 32];
#pragma unroll
            for (int t = 0; t < 8; t++) { accA[t] += cfa * wa[t]; accB[t] += cfb * wb[t]; }
        }
    }

    // vector x vector -> 8x0e : w2 at 2048 + (u*8+v)*8, coef (lv.rv)/sqrt3
#pragma unroll 1
    for (int u = 0; u < 8; u++) {
        float la0 = shL[(16 + u * 3) * EPB + lane];
        float la1 = shL[(17 + u * 3) * EPB + lane];
        float la2 = shL[(18 + u * 3) * EPB + lane];
        float lb0 = shL[(16 + u * 3) * EPB + lane + 32];
        float lb1 = shL[(17 + u * 3) * EPB + lane + 32];
        float lb2 = shL[(18 + u * 3) * EPB + lane + 32];
#pragma unroll 1
        for (int v = 0; v < 8; v++) {
            float wa[8], wb[8];
#pragma unroll
            for (int t = 0; t < 8; t++) { wa[t] = 0.0f; wb[t] = 0.0f; }
            const float* base = Wk + 2048 + (u * 8 + v) * 8;
#pragma unroll 4
            for (int j = 0; j < KC; j++) {
                const float4* p = reinterpret_cast<const float4*>(base + j * 2560);
                float4 q0 = __ldg(p), q1 = __ldg(p + 1);
                float A = ha[j], Bv = hb[j];
                wa[0]+=A*q0.x; wa[1]+=A*q0.y; wa[2]+=A*q0.z; wa[3]+=A*q0.w;
                wa[4]+=A*q1.x; wa[5]+=A*q1.y; wa[6]+=A*q1.z; wa[7]+=A*q1.w;
                wb[0]+=Bv*q0.x; wb[1]+=Bv*q0.y; wb[2]+=Bv*q0.z; wb[3]+=Bv*q0.w;
                wb[4]+=Bv*q1.x; wb[5]+=Bv*q1.y; wb[6]+=Bv*q1.z; wb[7]+=Bv*q1.w;
            }
            float cfa = (la0 * shRn[(16 + v * 3) * EPB + lane] +
                         la1 * shRn[(17 + v * 3) * EPB + lane] +
                         la2 * shRn[(18 + v * 3) * EPB + lane]) * INVS3;
            float cfb = (lb0 * shRn[(16 + v * 3) * EPB + lane + 32] +
                         lb1 * shRn[(17 + v * 3) * EPB + lane + 32] +
                         lb2 * shRn[(18 + v * 3) * EPB + lane + 32]) * INVS3;
#pragma unroll
            for (int t = 0; t < 8; t++) { accA[t] += cfa * wa[t]; accB[t] += cfb * wb[t]; }
        }
    }

    float* slice = shS + warp * 8 * EPB;
#pragma unroll
    for (int t = 0; t < 8; t++) {
        slice[t * EPB + lane]      = accA[t];
        slice[t * EPB + lane + 32] = accB[t];
    }
    __syncthreads();

    for (int i = tid; i < 8 * EPB; i += TBE) {
        int e = i & (EPB - 1), f = i >> 6;
        float s = shS[i] + shS[8 * EPB + i] + shS[16 * EPB + i] + shS[24 * EPB + i];
        if (e0 + e < EI) out[(e0 + e) * 8 + f] = PWREC * s;
    }
}

// ---------------------------------------------------------------------------
// host launcher (graph-capturable: kernel launches only)
// ---------------------------------------------------------------------------
extern "C" void kernel_launch(void* const* d_in, const int* in_sizes, int n_in,
                              void* d_out, int out_size) {
    (void)n_in; (void)out_size;
    const float* x       = (const float*)d_in[0];
    const float* pos     = (const float*)d_in[1];
    const int*   eidx    = (const int*)  d_in[2];
    const float* eattr   = (const float*)d_in[3];
    const int*   iidx    = (const int*)  d_in[4];
    const float* emb_w0  = (const float*)d_in[5];
    const float* emb_w1  = (const float*)d_in[6];
    const float* imp0    = (const float*)d_in[7];
    const float* msg0_w0 = (const float*)d_in[8];
    const float* msg0_w1 = (const float*)d_in[9];
    const float* upd0_w0 = (const float*)d_in[10];
    const float* upd0_w1 = (const float*)d_in[11];
    const float* imp1    = (const float*)d_in[12];
    const float* msg1_w0 = (const float*)d_in[13];
    const float* msg1_w1 = (const float*)d_in[14];
    const float* upd1_w0 = (const float*)d_in[15];
    const float* upd1_w1 = (const float*)d_in[16];
    const float* lig_w0  = (const float*)d_in[17];
    const float* lig_w1  = (const float*)d_in[18];
    const float* rec_w0  = (const float*)d_in[19];
    const float* rec_w1  = (const float*)d_in[20];

    int N  = in_sizes[1] / 3;
    int A  = in_sizes[0] / N;
    int E  = in_sizes[2] / 2;
    int B  = in_sizes[3] / E;
    int EI = in_sizes[4] / 2;
    const int* src  = eidx;
    const int* dst  = eidx + E;
    const int* recI = iidx;
    const int* ligI = iidx + EI;
    float degf = (float)E / (float)N;

    int gn = (N + 127) / 128;
    int ge = (E + EPB - 1) / EPB;
    int gi = (EI + EPB - 1) / EPB;

    k_embed<<<gn, 128>>>(x, N, A, emb_w0, emb_w1);      // also zeroes g_msgs

    k_msg<<<ge, TBE>>>(pos, src, dst, eattr, E, B, msg0_w0, msg0_w1);
    k_update<<<gn, 128>>>(N, imp0, degf, upd0_w0, upd0_w1, 1.0f);  // re-zeroes g_msgs

    k_msg<<<ge, TBE>>>(pos, src, dst, eattr, E, B, msg1_w0, msg1_w1);
    k_update<<<gn, 128>>>(N, imp1, degf, upd1_w0, upd1_w1, 0.5f);

    k_lig<<<gi, TBE>>>(pos, recI, ligI, EI, lig_w0, lig_w1);
    k_rec<<<gi, TBE>>>(pos, recI, ligI, EI, rec_w0, rec_w1, (float*)d_out);
}

// round 8
// speedup vs baseline: 1.3325x; 1.3325x over previous
#include <cuda_runtime.h>
#include <math.h>

// ---------------------------------------------------------------------------
// InteractionPredictor: e3nn-style equivariant GNN, fully fused fp32.
// R7: R5 skeleton (64 edges / 256 threads, 8 warps x KC=8, 2 edges/lane)
// with the smem-atomic cross-warp reduction replaced by non-atomic per-warp
// slices + cooperative tree-add, phased (scalar 16f, vector 2x12f) to fit
// 48KB static smem and keep register pressure at R5 levels.
// ---------------------------------------------------------------------------

#define TBE    256         /* threads per edge block      */
#define EPB    64          /* edges per block             */
#define KC     8           /* k-chunk per warp (8 warps)  */
#define NW     8           /* warps per block             */
#define NF     40
#define NMAX   16384
#define EIMAX  65536

__device__ float g_node[NMAX * NF];
__device__ float g_msgs[NMAX * NF];
__device__ float g_lig [EIMAX * NF];

#define C24    0.20412414523193154f   /* sqrt(1/24)  */
#define C24S3  0.35355339059327373f   /* sqrt(1/8)   */
#define INVS3  0.57735026918962576f   /* 1/sqrt(3)   */
#define PWREC  0.05590169943749474f   /* 1/sqrt(320) */
#define DEMBC  8.4335731f             /* 1.14136*e^2 */
#define INV32  0.17677669529663687f   /* 1/sqrt(32)  */

__device__ __forceinline__ float siluN(float x) {
    return x * (1.0f / (1.0f + __expf(-x))) * 1.6789717f;
}

// ---------------------------------------------------------------------------
// node embedding; also zeroes the message accumulator for step 0
// ---------------------------------------------------------------------------
__global__ void k_embed(const float* __restrict__ x, int N, int A,
                        const float* __restrict__ W0, const float* __restrict__ W1) {
    int n = blockIdx.x * blockDim.x + threadIdx.x;
    if (n >= N) return;
    float inv = rsqrtf((float)A);
    float a[16];
#pragma unroll
    for (int b = 0; b < 16; b++) a[b] = (b < A) ? x[n * A + b] : 0.0f;
    float h[64];
#pragma unroll 4
    for (int k = 0; k < 64; k++) {
        float s = 0.0f;
#pragma unroll
        for (int b = 0; b < 16; b++)
            if (b < A) s += a[b] * W0[b * 64 + k];
        h[k] = siluN(s * inv) * 0.125f;
    }
    float* nr = g_node + n * NF;
#pragma unroll
    for (int w = 0; w < 16; w++) {
        float s = 0.0f;
#pragma unroll 8
        for (int k = 0; k < 64; k++) s += h[k] * W1[k * 16 + w];
        nr[w] = s;
    }
#pragma unroll
    for (int t = 0; t < 24; t++) nr[16 + t] = 0.0f;
    float* mr = g_msgs + n * NF;
#pragma unroll
    for (int t = 0; t < NF; t++) mr[t] = 0.0f;
}

// ---------------------------------------------------------------------------
// node update; re-zeroes this node's message row after consuming it
// ---------------------------------------------------------------------------
__global__ void k_update(int N, const float* __restrict__ imp, float degf,
                         const float* __restrict__ W0, const float* __restrict__ W1,
                         float gmul) {
    int n = blockIdx.x * blockDim.x + threadIdx.x;
    if (n >= N) return;
    float scale = imp[0] * rsqrtf(degf);
    float* nr = g_node + n * NF;
    float* mr = g_msgs + n * NF;
    float a[32];
#pragma unroll
    for (int t = 0; t < 16; t++) a[t] = mr[t] * scale;
#pragma unroll
    for (int t = 0; t < 16; t++) a[16 + t] = nr[t];
    float ge[24];
#pragma unroll
    for (int t = 0; t < 24; t++) ge[t] = (mr[16 + t] * scale + nr[16 + t]) * gmul;
#pragma unroll
    for (int t = 0; t < NF; t++) mr[t] = 0.0f;
    float h[64];
#pragma unroll 2
    for (int k = 0; k < 64; k++) {
        float s = 0.0f;
#pragma unroll
        for (int b = 0; b < 32; b++) s += a[b] * W0[b * 64 + k];
        h[k] = siluN(s * INV32) * 0.125f;
    }
    float sc[16];
#pragma unroll
    for (int w = 0; w < 16; w++) {
        float s = 0.0f;
#pragma unroll 8
        for (int k = 0; k < 64; k++) s += h[k] * W1[k * 16 + w];
        sc[w] = s;
    }
#pragma unroll
    for (int w = 0; w < 16; w++) nr[w] = sc[w];
#pragma unroll
    for (int t = 0; t < 24; t++) nr[16 + t] = ge[t];
}

// ---------------------------------------------------------------------------
__device__ __forceinline__ void demb_compute(float d, float* a) {
    float tt = d * 4.2f;
#pragma unroll
    for (int i = 0; i < 20; i++) {
        float diff = tt - (float)(i + 1);
        float p = diff + 1.0f, q = 1.0f - diff;
        float s1 = (p > 0.0f) ? __expf(-1.0f / p) : 0.0f;
        float s2 = (q > 0.0f) ? __expf(-1.0f / q) : 0.0f;
        a[i] = DEMBC * s1 * s2;
    }
}

// ---------------------------------------------------------------------------
// Scalar-output fold (blocks A+B -> 16 features); writes this warp's slice.
// ---------------------------------------------------------------------------
__device__ __forceinline__ void fold_scalar(
    const float* __restrict__ ha, const float* __restrict__ hb, int lane,
    const float* __restrict__ shN, const float* __restrict__ shR,
    const float* __restrict__ W1k, float* __restrict__ slice)
{
    float ra0 = shR[lane],      ra1 = shR[EPB + lane],      ra2 = shR[2 * EPB + lane];
    float rb0 = shR[lane + 32], rb1 = shR[EPB + lane + 32], rb2 = shR[2 * EPB + lane + 32];

    float osA[16], osB[16];
#pragma unroll
    for (int t = 0; t < 16; t++) { osA[t] = 0.0f; osB[t] = 0.0f; }

    // Block A: 0e x 0e -> 0e ; cols [u*16, +16), u<16
#pragma unroll 1
    for (int u = 0; u < 16; u++) {
        float wa[16], wb[16];
#pragma unroll
        for (int t = 0; t < 16; t++) { wa[t] = 0.0f; wb[t] = 0.0f; }
        const float* base = W1k + u * 16;
#pragma unroll
        for (int j = 0; j < KC; j++) {
            const float4* p = reinterpret_cast<const float4*>(base + j * 576);
            float4 q0 = __ldg(p), q1 = __ldg(p + 1), q2 = __ldg(p + 2), q3 = __ldg(p + 3);
            float A = ha[j], Bv = hb[j];
            wa[0]+=A*q0.x; wa[1]+=A*q0.y; wa[2]+=A*q0.z; wa[3]+=A*q0.w;
            wa[4]+=A*q1.x; wa[5]+=A*q1.y; wa[6]+=A*q1.z; wa[7]+=A*q1.w;
            wa[8]+=A*q2.x; wa[9]+=A*q2.y; wa[10]+=A*q2.z; wa[11]+=A*q2.w;
            wa[12]+=A*q3.x; wa[13]+=A*q3.y; wa[14]+=A*q3.z; wa[15]+=A*q3.w;
            wb[0]+=Bv*q0.x; wb[1]+=Bv*q0.y; wb[2]+=Bv*q0.z; wb[3]+=Bv*q0.w;
            wb[4]+=Bv*q1.x; wb[5]+=Bv*q1.y; wb[6]+=Bv*q1.z; wb[7]+=Bv*q1.w;
            wb[8]+=Bv*q2.x; wb[9]+=Bv*q2.y; wb[10]+=Bv*q2.z; wb[11]+=Bv*q2.w;
            wb[12]+=Bv*q3.x; wb[13]+=Bv*q3.y; wb[14]+=Bv*q3.z; wb[15]+=Bv*q3.w;
        }
        float cfa = C24 * shN[u * EPB + lane];
        float cfb = C24 * shN[u * EPB + lane + 32];
#pragma unroll
        for (int t = 0; t < 16; t++) { osA[t] += cfa * wa[t]; osB[t] += cfb * wb[t]; }
    }

    // Block B: 1o x 1o -> 0e ; cols [256+u*16), u<8 ; coef C24*(xv_u . r)
#pragma unroll 1
    for (int u = 0; u < 8; u++) {
        float wa[16], wb[16];
#pragma unroll
        for (int t = 0; t < 16; t++) { wa[t] = 0.0f; wb[t] = 0.0f; }
        const float* base = W1k + 256 + u * 16;
#pragma unroll
        for (int j = 0; j < KC; j++) {
            const float4* p = reinterpret_cast<const float4*>(base + j * 576);
            float4 q0 = __ldg(p), q1 = __ldg(p + 1), q2 = __ldg(p + 2), q3 = __ldg(p + 3);
            float A = ha[j], Bv = hb[j];
            wa[0]+=A*q0.x; wa[1]+=A*q0.y; wa[2]+=A*q0.z; wa[3]+=A*q0.w;
            wa[4]+=A*q1.x; wa[5]+=A*q1.y; wa[6]+=A*q1.z; wa[7]+=A*q1.w;
            wa[8]+=A*q2.x; wa[9]+=A*q2.y; wa[10]+=A*q2.z; wa[11]+=A*q2.w;
            wa[12]+=A*q3.x; wa[13]+=A*q3.y; wa[14]+=A*q3.z; wa[15]+=A*q3.w;
            wb[0]+=Bv*q0.x; wb[1]+=Bv*q0.y; wb[2]+=Bv*q0.z; wb[3]+=Bv*q0.w;
            wb[4]+=Bv*q1.x; wb[5]+=Bv*q1.y; wb[6]+=Bv*q1.z; wb[7]+=Bv*q1.w;
            wb[8]+=Bv*q2.x; wb[9]+=Bv*q2.y; wb[10]+=Bv*q2.z; wb[11]+=Bv*q2.w;
            wb[12]+=Bv*q3.x; wb[13]+=Bv*q3.y; wb[14]+=Bv*q3.z; wb[15]+=Bv*q3.w;
        }
        float cfa = C24 * (shN[(16 + u * 3) * EPB + lane] * ra0 +
                           shN[(17 + u * 3) * EPB + lane] * ra1 +
                           shN[(18 + u * 3) * EPB + lane] * ra2);
        float cfb = C24 * (shN[(16 + u * 3) * EPB + lane + 32] * rb0 +
                           shN[(17 + u * 3) * EPB + lane + 32] * rb1 +
                           shN[(18 + u * 3) * EPB + lane + 32] * rb2);
#pragma unroll
        for (int t = 0; t < 16; t++) { osA[t] += cfa * wa[t]; osB[t] += cfb * wb[t]; }
    }

#pragma unroll
    for (int t = 0; t < 16; t++) {
        slice[t * EPB + lane]      = osA[t];
        slice[t * EPB + lane + 32] = osB[t];
    }
}

// ---------------------------------------------------------------------------
// Vector-output fold, one half (4 of the 8 vector mults -> 12 features).
// half=0 -> t 0..3 (q0 of each float4 pair), half=1 -> t 4..7 (q1).
// ---------------------------------------------------------------------------
__device__ __forceinline__ void fold_vector_half(
    const float* __restrict__ ha, const float* __restrict__ hb, int lane,
    const float* __restrict__ shN, const float* __restrict__ shR, int half,
    const float* __restrict__ W1k, float* __restrict__ slice)
{
    float ra0 = shR[lane],      ra1 = shR[EPB + lane],      ra2 = shR[2 * EPB + lane];
    float rb0 = shR[lane + 32], rb1 = shR[EPB + lane + 32], rb2 = shR[2 * EPB + lane + 32];

    float ovA[12], ovB[12];
#pragma unroll
    for (int t = 0; t < 12; t++) { ovA[t] = 0.0f; ovB[t] = 0.0f; }

    // Block C: 0e x 1o -> 1o ; cols [384 + u*8 + half*4), u<16
#pragma unroll 1
    for (int u = 0; u < 16; u++) {
        float wa[4], wb[4];
#pragma unroll
        for (int t = 0; t < 4; t++) { wa[t] = 0.0f; wb[t] = 0.0f; }
        const float* base = W1k + 384 + u * 8 + half * 4;
#pragma unroll
        for (int j = 0; j < KC; j++) {
            float4 q = __ldg(reinterpret_cast<const float4*>(base + j * 576));
            float A = ha[j], Bv = hb[j];
            wa[0]+=A*q.x; wa[1]+=A*q.y; wa[2]+=A*q.z; wa[3]+=A*q.w;
            wb[0]+=Bv*q.x; wb[1]+=Bv*q.y; wb[2]+=Bv*q.z; wb[3]+=Bv*q.w;
        }
        float cfa = C24S3 * shN[u * EPB + lane];
        float cfb = C24S3 * shN[u * EPB + lane + 32];
#pragma unroll
        for (int t = 0; t < 4; t++) {
            float sa = cfa * wa[t], sb = cfb * wb[t];
            ovA[t*3+0] += sa * ra0; ovA[t*3+1] += sa * ra1; ovA[t*3+2] += sa * ra2;
            ovB[t*3+0] += sb * rb0; ovB[t*3+1] += sb * rb1; ovB[t*3+2] += sb * rb2;
        }
    }

    // Block D: 1o x 0e -> 1o ; cols [512 + u*8 + half*4), u<8
#pragma unroll 1
    for (int u = 0; u < 8; u++) {
        float wa[4], wb[4];
#pragma unroll
        for (int t = 0; t < 4; t++) { wa[t] = 0.0f; wb[t] = 0.0f; }
        const float* base = W1k + 512 + u * 8 + half * 4;
#pragma unroll
        for (int j = 0; j < KC; j++) {
            float4 q = __ldg(reinterpret_cast<const float4*>(base + j * 576));
            float A = ha[j], Bv = hb[j];
            wa[0]+=A*q.x; wa[1]+=A*q.y; wa[2]+=A*q.z; wa[3]+=A*q.w;
            wb[0]+=Bv*q.x; wb[1]+=Bv*q.y; wb[2]+=Bv*q.z; wb[3]+=Bv*q.w;
        }
        float ca0 = C24 * shN[(16 + u * 3) * EPB + lane];
        float ca1 = C24 * shN[(17 + u * 3) * EPB + lane];
        float ca2 = C24 * shN[(18 + u * 3) * EPB + lane];
        float cb0 = C24 * shN[(16 + u * 3) * EPB + lane + 32];
        float cb1 = C24 * shN[(17 + u * 3) * EPB + lane + 32];
        float cb2 = C24 * shN[(18 + u * 3) * EPB + lane + 32];
#pragma unroll
        for (int t = 0; t < 4; t++) {
            ovA[t*3+0] += ca0 * wa[t]; ovA[t*3+1] += ca1 * wa[t]; ovA[t*3+2] += ca2 * wa[t];
            ovB[t*3+0] += cb0 * wb[t]; ovB[t*3+1] += cb1 * wb[t]; ovB[t*3+2] += cb2 * wb[t];
        }
    }

#pragma unroll
    for (int t = 0; t < 12; t++) {
        slice[t * EPB + lane]      = ovA[t];
        slice[t * EPB + lane + 32] = ovB[t];
    }
}

// ---------------------------------------------------------------------------
// message kernel: 64 edges / 256 threads, 8 warps x KC=8, slice reduction
// ---------------------------------------------------------------------------
__global__ void __launch_bounds__(TBE, 2) k_msg(
    const float* __restrict__ pos,
    const int* __restrict__ srcI, const int* __restrict__ dstI,
    const float* __restrict__ eattr, int E, int B,
    const float* __restrict__ W0, const float* __restrict__ W1)
{
    __shared__ float shN[NF * EPB];          // 10 KB
    __shared__ float shS[NW * 16 * EPB];     // 32 KB (scalar 16f / vector 12f reuse)
    __shared__ float shR[3 * EPB];
    __shared__ int   shSi[EPB];
    __shared__ int   shDi[EPB];

    int tid  = threadIdx.x;
    int lane = tid & 31;
    int warp = tid >> 5;
    int e0 = blockIdx.x * EPB;

    if (tid < EPB) {
        int e = min(e0 + tid, E - 1);
        int si = srcI[e], di = dstI[e];
        shSi[tid] = si; shDi[tid] = di;
        float vx = pos[di * 3 + 0] - pos[si * 3 + 0];
        float vy = pos[di * 3 + 1] - pos[si * 3 + 1];
        float vz = pos[di * 3 + 2] - pos[si * 3 + 2];
        float rn = rsqrtf(vx * vx + vy * vy + vz * vz);
        shR[tid]           = vx * rn;
        shR[EPB + tid]     = vy * rn;
        shR[2 * EPB + tid] = vz * rn;
    }
    __syncthreads();

    // preload source-node features [f][e]
    for (int i = tid; i < NF * EPB; i += TBE) {
        int e = i & (EPB - 1), f = i >> 6;
        shN[f * EPB + e] = g_node[shSi[e] * NF + f];
    }

    // this warp's k-chunk of h (registers, both edges)
    float ha[KC], hb[KC];
    {
        float inv = rsqrtf((float)B);
        int kb = warp * KC;
        int ea = min(e0 + lane, E - 1);
        int eb = min(e0 + lane + 32, E - 1);
        float aa[8], ab[8];
#pragma unroll
        for (int b = 0; b < 8; b++) {
            aa[b] = (b < B) ? eattr[ea * B + b] : 0.0f;
            ab[b] = (b < B) ? eattr[eb * B + b] : 0.0f;
        }
#pragma unroll
        for (int j = 0; j < KC; j++) {
            float sa = 0.0f, sb = 0.0f;
#pragma unroll
            for (int b = 0; b < 8; b++)
                if (b < B) {
                    float w = W0[b * 64 + kb + j];
                    sa += aa[b] * w; sb += ab[b] * w;
                }
            ha[j] = siluN(sa * inv) * 0.125f;
            hb[j] = siluN(sb * inv) * 0.125f;
        }
    }
    __syncthreads();

    const float* W1k = W1 + warp * KC * 576;

    // ---- scalar phase ----
    fold_scalar(ha, hb, lane, shN, shR, W1k, shS + warp * 16 * EPB);
    __syncthreads();
    for (int i = tid; i < 16 * EPB; i += TBE) {
        float s = 0.0f;
#pragma unroll
        for (int w = 0; w < NW; w++) s += shS[w * 16 * EPB + i];
        int e = i & (EPB - 1), f = i >> 6;
        if (e0 + e < E) atomicAdd(&g_msgs[shDi[e] * NF + f], s);
    }
    __syncthreads();

    // ---- vector phases (2 halves of 12 features) ----
#pragma unroll 1
    for (int half = 0; half < 2; half++) {
        fold_vector_half(ha, hb, lane, shN, shR, half, W1k, shS + warp * 12 * EPB);
        __syncthreads();
        for (int i = tid; i < 12 * EPB; i += TBE) {
            float s = 0.0f;
#pragma unroll
            for (int w = 0; w < NW; w++) s += shS[w * 12 * EPB + i];
            int e = i & (EPB - 1), f = i >> 6;
            if (e0 + e < E) atomicAdd(&g_msgs[shDi[e] * NF + 16 + half * 12 + f], s);
        }
        __syncthreads();
    }
}

// ---------------------------------------------------------------------------
// ligand embedding
// ---------------------------------------------------------------------------
__global__ void __launch_bounds__(TBE, 2) k_lig(
    const float* __restrict__ pos,
    const int* __restrict__ recI, const int* __restrict__ ligI, int EI,
    const float* __restrict__ W0, const float* __restrict__ W1)
{
    __shared__ float shN[NF * EPB];
    __shared__ float shS[NW * 16 * EPB];
    __shared__ float shR[3 * EPB];
    __shared__ float shD[EPB];
    __shared__ int   shLi[EPB];

    int tid  = threadIdx.x;
    int lane = tid & 31;
    int warp = tid >> 5;
    int e0 = blockIdx.x * EPB;

    if (tid < EPB) {
        int e = min(e0 + tid, EI - 1);
        int ri = recI[e], li = ligI[e];
        shLi[tid] = li;
        float vx = pos[li * 3 + 0] - pos[ri * 3 + 0];
        float vy = pos[li * 3 + 1] - pos[ri * 3 + 1];
        float vz = pos[li * 3 + 2] - pos[ri * 3 + 2];
        float d2 = vx * vx + vy * vy + vz * vz;
        float invd = rsqrtf(d2);
        shR[tid]           = vx * invd;
        shR[EPB + tid]     = vy * invd;
        shR[2 * EPB + tid] = vz * invd;
        shD[tid]           = d2 * invd;
    }
    __syncthreads();

    for (int i = tid; i < NF * EPB; i += TBE) {
        int e = i & (EPB - 1), f = i >> 6;
        shN[f * EPB + e] = g_node[shLi[e] * NF + f];
    }

    float ha[KC], hb[KC];
    {
        int kb = warp * KC;
        float aa[20], ab[20];
        demb_compute(shD[lane],      aa);
        demb_compute(shD[lane + 32], ab);
#pragma unroll
        for (int j = 0; j < KC; j++) {
            float sa = 0.0f, sb = 0.0f;
#pragma unroll
            for (int i = 0; i < 20; i++) {
                float w = W0[i * 64 + kb + j];
                sa += aa[i] * w; sb += ab[i] * w;
            }
            ha[j] = siluN(sa) * 0.125f;
            hb[j] = siluN(sb) * 0.125f;
        }
    }
    __syncthreads();

    const float* W1k = W1 + warp * KC * 576;

    fold_scalar(ha, hb, lane, shN, shR, W1k, shS + warp * 16 * EPB);
    __syncthreads();
    for (int i = tid; i < 16 * EPB; i += TBE) {
        float s = 0.0f;
#pragma unroll
        for (int w = 0; w < NW; w++) s += shS[w * 16 * EPB + i];
        int e = i & (EPB - 1), f = i >> 6;
        if (e0 + e < EI) g_lig[(e0 + e) * NF + f] = s;
    }
    __syncthreads();

#pragma unroll 1
    for (int half = 0; half < 2; half++) {
        fold_vector_half(ha, hb, lane, shN, shR, half, W1k, shS + warp * 12 * EPB);
        __syncthreads();
        for (int i = tid; i < 12 * EPB; i += TBE) {
            float s = 0.0f;
#pragma unroll
            for (int w = 0; w < NW; w++) s += shS[w * 12 * EPB + i];
            int e = i & (EPB - 1), f = i >> 6;
            if (e0 + e < EI) g_lig[(e0 + e) * NF + 16 + half * 12 + f] = s;
        }
        __syncthreads();
    }
}

// ---------------------------------------------------------------------------
// receptor TP readout: out[e][o], o<8 (single-phase slice reduction)
// ---------------------------------------------------------------------------
__global__ void __launch_bounds__(TBE, 2) k_rec(
    const float* __restrict__ pos,
    const int* __restrict__ recI, const int* __restrict__ ligI, int EI,
    const float* __restrict__ W0, const float* __restrict__ W1,
    float* __restrict__ out)
{
    __shared__ float shL [NF * EPB];
    __shared__ float shRn[NF * EPB];
    __shared__ float shS [NW * 8 * EPB];    // 16 KB
    __shared__ float shD [EPB];
    __shared__ int   shRi[EPB];

    int tid  = threadIdx.x;
    int lane = tid & 31;
    int warp = tid >> 5;
    int e0 = blockIdx.x * EPB;

    if (tid < EPB) {
        int e = min(e0 + tid, EI - 1);
        int ri = recI[e], li = ligI[e];
        shRi[tid] = ri;
        float vx = pos[li * 3 + 0] - pos[ri * 3 + 0];
        float vy = pos[li * 3 + 1] - pos[ri * 3 + 1];
        float vz = pos[li * 3 + 2] - pos[ri * 3 + 2];
        float d2 = vx * vx + vy * vy + vz * vz;
        shD[tid] = d2 * rsqrtf(d2);
    }
    __syncthreads();

    for (int i = tid; i < NF * EPB; i += TBE) {
        int e = i & (EPB - 1), f = i >> 6;
        int ec = min(e0 + e, EI - 1);
        shL [f * EPB + e] = g_lig[ec * NF + f];
        shRn[f * EPB + e] = g_node[shRi[e] * NF + f];
    }

    float ha[KC], hb[KC];
    {
        int kb = warp * KC;
        float aa[20], ab[20];
        demb_compute(shD[lane],      aa);
        demb_compute(shD[lane + 32], ab);
#pragma unroll
        for (int j = 0; j < KC; j++) {
            float sa = 0.0f, sb = 0.0f;
#pragma unroll
            for (int i = 0; i < 20; i++) {
                float w = W0[i * 64 + kb + j];
                sa += aa[i] * w; sb += ab[i] * w;
            }
            ha[j] = siluN(sa) * 0.125f;
            hb[j] = siluN(sb) * 0.125f;
        }
    }
    __syncthreads();

    float accA[8], accB[8];
#pragma unroll
    for (int t = 0; t < 8; t++) { accA[t] = 0.0f; accB[t] = 0.0f; }
    const float* Wk = W1 + warp * KC * 2560;

    // scalar x scalar -> 8x0e : w1[u][v][o] at (u*16+v)*8
#pragma unroll 1
    for (int u = 0; u < 16; u++) {
        float lua = shL[u * EPB + lane];
        float lub = shL[u * EPB + lane + 32];
#pragma unroll 1
        for (int v = 0; v < 16; v++) {
            float wa[8], wb[8];
#pragma unroll
            for (int t = 0; t < 8; t++) { wa[t] = 0.0f; wb[t] = 0.0f; }
            const float* base = Wk + (u * 16 + v) * 8;
#pragma unroll
            for (int j = 0; j < KC; j++) {
                const float4* p = reinterpret_cast<const float4*>(base + j * 2560);
                float4 q0 = __ldg(p), q1 = __ldg(p + 1);
                float A = ha[j], Bv = hb[j];
                wa[0]+=A*q0.x; wa[1]+=A*q0.y; wa[2]+=A*q0.z; wa[3]+=A*q0.w;
                wa[4]+=A*q1.x; wa[5]+=A*q1.y; wa[6]+=A*q1.z; wa[7]+=A*q1.w;
                wb[0]+=Bv*q0.x; wb[1]+=Bv*q0.y; wb[2]+=Bv*q0.z; wb[3]+=Bv*q0.w;
                wb[4]+=Bv*q1.x; wb[5]+=Bv*q1.y; wb[6]+=Bv*q1.z; wb[7]+=Bv*q1.w;
            }
            float cfa = lua * shRn[v * EPB + lane];
            float cfb = lub * shRn[v * EPB + lane + 32];
#pragma unroll
            for (int t = 0; t < 8; t++) { accA[t] += cfa * wa[t]; accB[t] += cfb * wb[t]; }
        }
    }

    // vector x vector -> 8x0e : w2 at 2048 + (u*8+v)*8, coef (lv.rv)/sqrt3
#pragma unroll 1
    for (int u = 0; u < 8; u++) {
        float la0 = shL[(16 + u * 3) * EPB + lane];
        float la1 = shL[(17 + u * 3) * EPB + lane];
        float la2 = shL[(18 + u * 3) * EPB + lane];
        float lb0 = shL[(16 + u * 3) * EPB + lane + 32];
        float lb1 = shL[(17 + u * 3) * EPB + lane + 32];
        float lb2 = shL[(18 + u * 3) * EPB + lane + 32];
#pragma unroll 1
        for (int v = 0; v < 8; v++) {
            float wa[8], wb[8];
#pragma unroll
            for (int t = 0; t < 8; t++) { wa[t] = 0.0f; wb[t] = 0.0f; }
            const float* base = Wk + 2048 + (u * 8 + v) * 8;
#pragma unroll
            for (int j = 0; j < KC; j++) {
                const float4* p = reinterpret_cast<const float4*>(base + j * 2560);
                float4 q0 = __ldg(p), q1 = __ldg(p + 1);
                float A = ha[j], Bv = hb[j];
                wa[0]+=A*q0.x; wa[1]+=A*q0.y; wa[2]+=A*q0.z; wa[3]+=A*q0.w;
                wa[4]+=A*q1.x; wa[5]+=A*q1.y; wa[6]+=A*q1.z; wa[7]+=A*q1.w;
                wb[0]+=Bv*q0.x; wb[1]+=Bv*q0.y; wb[2]+=Bv*q0.z; wb[3]+=Bv*q0.w;
                wb[4]+=Bv*q1.x; wb[5]+=Bv*q1.y; wb[6]+=Bv*q1.z; wb[7]+=Bv*q1.w;
            }
            float cfa = (la0 * shRn[(16 + v * 3) * EPB + lane] +
                         la1 * shRn[(17 + v * 3) * EPB + lane] +
                         la2 * shRn[(18 + v * 3) * EPB + lane]) * INVS3;
            float cfb = (lb0 * shRn[(16 + v * 3) * EPB + lane + 32] +
                         lb1 * shRn[(17 + v * 3) * EPB + lane + 32] +
                         lb2 * shRn[(18 + v * 3) * EPB + lane + 32]) * INVS3;
#pragma unroll
            for (int t = 0; t < 8; t++) { accA[t] += cfa * wa[t]; accB[t] += cfb * wb[t]; }
        }
    }

    float* slice = shS + warp * 8 * EPB;
#pragma unroll
    for (int t = 0; t < 8; t++) {
        slice[t * EPB + lane]      = accA[t];
        slice[t * EPB + lane + 32] = accB[t];
    }
    __syncthreads();

    for (int i = tid; i < 8 * EPB; i += TBE) {
        float s = 0.0f;
#pragma unroll
        for (int w = 0; w < NW; w++) s += shS[w * 8 * EPB + i];
        int e = i & (EPB - 1), f = i >> 6;
        if (e0 + e < EI) out[(e0 + e) * 8 + f] = PWREC * s;
    }
}

// ---------------------------------------------------------------------------
// host launcher (graph-capturable: kernel launches only)
// ---------------------------------------------------------------------------
extern "C" void kernel_launch(void* const* d_in, const int* in_sizes, int n_in,
                              void* d_out, int out_size) {
    (void)n_in; (void)out_size;
    const float* x       = (const float*)d_in[0];
    const float* pos     = (const float*)d_in[1];
    const int*   eidx    = (const int*)  d_in[2];
    const float* eattr   = (const float*)d_in[3];
    const int*   iidx    = (const int*)  d_in[4];
    const float* emb_w0  = (const float*)d_in[5];
    const float* emb_w1  = (const float*)d_in[6];
    const float* imp0    = (const float*)d_in[7];
    const float* msg0_w0 = (const float*)d_in[8];
    const float* msg0_w1 = (const float*)d_in[9];
    const float* upd0_w0 = (const float*)d_in[10];
    const float* upd0_w1 = (const float*)d_in[11];
    const float* imp1    = (const float*)d_in[12];
    const float* msg1_w0 = (const float*)d_in[13];
    const float* msg1_w1 = (const float*)d_in[14];
    const float* upd1_w0 = (const float*)d_in[15];
    const float* upd1_w1 = (const float*)d_in[16];
    const float* lig_w0  = (const float*)d_in[17];
    const float* lig_w1  = (const float*)d_in[18];
    const float* rec_w0  = (const float*)d_in[19];
    const float* rec_w1  = (const float*)d_in[20];

    int N  = in_sizes[1] / 3;
    int A  = in_sizes[0] / N;
    int E  = in_sizes[2] / 2;
    int B  = in_sizes[3] / E;
    int EI = in_sizes[4] / 2;
    const int* src  = eidx;
    const int* dst  = eidx + E;
    const int* recI = iidx;
    const int* ligI = iidx + EI;
    float degf = (float)E / (float)N;

    int gn = (N + 127) / 128;
    int ge = (E + EPB - 1) / EPB;
    int gi = (EI + EPB - 1) / EPB;

    k_embed<<<gn, 128>>>(x, N, A, emb_w0, emb_w1);      // also zeroes g_msgs

    k_msg<<<ge, TBE>>>(pos, src, dst, eattr, E, B, msg0_w0, msg0_w1);
    k_update<<<gn, 128>>>(N, imp0, degf, upd0_w0, upd0_w1, 1.0f);  // re-zeroes g_msgs

    k_msg<<<ge, TBE>>>(pos, src, dst, eattr, E, B, msg1_w0, msg1_w1);
    k_update<<<gn, 128>>>(N, imp1, degf, upd1_w0, upd1_w1, 0.5f);

    k_lig<<<gi, TBE>>>(pos, recI, ligI, EI, lig_w0, lig_w1);
    k_rec<<<gi, TBE>>>(pos, recI, ligI, EI, rec_w0, rec_w1, (float*)d_out);
}